// round 2
// baseline (speedup 1.0000x reference)
#include <cuda_runtime.h>
#include <math.h>

#define IN_DIM   256
#define OUT_DIM  64
#define NUM_HEADS 8
#define BATCH    8
#define SEQ      1024
#define QKV_COLS (OUT_DIM * NUM_HEADS)   // 512
#define ROWS     (BATCH * SEQ)           // 8192

// Scratch for projected Q/K/V: [B*N, H*D] each (16 MB apiece).
__device__ float g_Q[ROWS * QKV_COLS];
__device__ float g_K[ROWS * QKV_COLS];
__device__ float g_V[ROWS * QKV_COLS];

// ---------------------------------------------------------------------------
// Kernel 1: QKV projection.  out = h @ W + b
// h: [8192, 256], W: [256, 512].  Block tile 64x64, k-tile 16, thread 4x4.
// blockIdx.z selects Q / K / V.
// ---------------------------------------------------------------------------
__global__ __launch_bounds__(256)
void qkv_gemm_kernel(const float* __restrict__ h,
                     const float* __restrict__ Wq, const float* __restrict__ bq,
                     const float* __restrict__ Wk, const float* __restrict__ bk,
                     const float* __restrict__ Wv, const float* __restrict__ bv)
{
    const int which = blockIdx.z;
    const float* __restrict__ W    = (which == 0) ? Wq : (which == 1) ? Wk : Wv;
    const float* __restrict__ bias = (which == 0) ? bq : (which == 1) ? bk : bv;
    float* __restrict__ out        = (which == 0) ? g_Q : (which == 1) ? g_K : g_V;

    __shared__ float As[16][68];   // k-major A tile  As[k][m]
    __shared__ float Bs[16][68];   // Bs[k][n]

    const int tid = threadIdx.x;
    const int tx = tid & 15;        // 0..15 -> n
    const int ty = tid >> 4;        // 0..15 -> m
    const int row0 = blockIdx.y * 64;
    const int col0 = blockIdx.x * 64;

    // loader indices
    const int arow = tid >> 2;            // 0..63
    const int acol = (tid & 3) * 4;       // 0,4,8,12
    const int brow = tid >> 4;            // 0..15
    const int bcol = (tid & 15) * 4;      // 0..60

    float acc[4][4] = {};

    for (int k0 = 0; k0 < IN_DIM; k0 += 16) {
        float4 a = *(const float4*)&h[(size_t)(row0 + arow) * IN_DIM + k0 + acol];
        As[acol + 0][arow] = a.x;
        As[acol + 1][arow] = a.y;
        As[acol + 2][arow] = a.z;
        As[acol + 3][arow] = a.w;
        float4 b = *(const float4*)&W[(size_t)(k0 + brow) * QKV_COLS + col0 + bcol];
        *(float4*)&Bs[brow][bcol] = b;
        __syncthreads();

        #pragma unroll
        for (int kk = 0; kk < 16; kk++) {
            float4 av = *(const float4*)&As[kk][ty * 4];
            float4 bv = *(const float4*)&Bs[kk][tx * 4];
            float am[4] = {av.x, av.y, av.z, av.w};
            float bn[4] = {bv.x, bv.y, bv.z, bv.w};
            #pragma unroll
            for (int i = 0; i < 4; i++)
                #pragma unroll
                for (int j = 0; j < 4; j++)
                    acc[i][j] = fmaf(am[i], bn[j], acc[i][j]);
        }
        __syncthreads();
    }

    // epilogue: + bias, vectorized store
    const int cbase = col0 + tx * 4;
    float4 bv4 = *(const float4*)&bias[cbase];
    #pragma unroll
    for (int i = 0; i < 4; i++) {
        int r = row0 + ty * 4 + i;
        float4 o;
        o.x = acc[i][0] + bv4.x;
        o.y = acc[i][1] + bv4.y;
        o.z = acc[i][2] + bv4.z;
        o.w = acc[i][3] + bv4.w;
        *(float4*)&out[(size_t)r * QKV_COLS + cbase] = o;
    }
}

// ---------------------------------------------------------------------------
// Kernel 2: fused masked attention (flash-style, fp32).
// One block per (64-query tile, head, batch).  256 threads, 4x4 per thread.
// ---------------------------------------------------------------------------
#define BR 64
#define BC 64
#define SSTR 68                      // smem row stride (floats), 16B-aligned rows

__global__ __launch_bounds__(256)
void attn_kernel(const int* __restrict__ adj, float* __restrict__ out)
{
    extern __shared__ float smem[];
    float* Qt = smem;                 // [64][SSTR]  Qt[d][r]
    float* Kt = Qt + 64 * SSTR;       // [64][SSTR]  Kt[d][c]
    float* Vs = Kt + 64 * SSTR;       // [64][SSTR]  Vs[c][d]
    float* Pt = Vs + 64 * SSTR;       // [64][SSTR]  Pt[c][r]

    const int b  = blockIdx.z;
    const int hd = blockIdx.y;
    const int q0 = blockIdx.x * BR;

    const int tid = threadIdx.x;
    const int tx = tid & 15;          // -> key-col group / dim group
    const int ty = tid >> 4;          // -> query-row group

    const float* __restrict__ Q = g_Q + ((size_t)b * SEQ) * QKV_COLS + hd * OUT_DIM;
    const float* __restrict__ K = g_K + ((size_t)b * SEQ) * QKV_COLS + hd * OUT_DIM;
    const float* __restrict__ V = g_V + ((size_t)b * SEQ) * QKV_COLS + hd * OUT_DIM;

    // ---- load Q tile transposed: Qt[d][r] ----
    #pragma unroll
    for (int c4 = 0; c4 < 4; c4++) {
        int lin = c4 * 256 + tid;            // float4 index 0..1023
        int r = lin >> 4;                    // 16 float4 per row
        int d = (lin & 15) * 4;
        float4 q = *(const float4*)&Q[(size_t)(q0 + r) * QKV_COLS + d];
        Qt[(d + 0) * SSTR + r] = q.x;
        Qt[(d + 1) * SSTR + r] = q.y;
        Qt[(d + 2) * SSTR + r] = q.z;
        Qt[(d + 3) * SSTR + r] = q.w;
    }

    const float scale = 0.125f;              // 1/sqrt(64)
    const float NEG = -1.0e30f;

    float m_i[4], l_i[4], acc[4][4];
    #pragma unroll
    for (int i = 0; i < 4; i++) {
        m_i[i] = NEG; l_i[i] = 0.f;
        #pragma unroll
        for (int j = 0; j < 4; j++) acc[i][j] = 0.f;
    }

    for (int m0 = 0; m0 < SEQ; m0 += BC) {
        // ---- load K tile transposed + V tile natural ----
        #pragma unroll
        for (int c4 = 0; c4 < 4; c4++) {
            int lin = c4 * 256 + tid;
            int r = lin >> 4;
            int d = (lin & 15) * 4;
            float4 k = *(const float4*)&K[(size_t)(m0 + r) * QKV_COLS + d];
            Kt[(d + 0) * SSTR + r] = k.x;
            Kt[(d + 1) * SSTR + r] = k.y;
            Kt[(d + 2) * SSTR + r] = k.z;
            Kt[(d + 3) * SSTR + r] = k.w;
            float4 v = *(const float4*)&V[(size_t)(m0 + r) * QKV_COLS + d];
            *(float4*)&Vs[r * SSTR + d] = v;
        }
        __syncthreads();

        // ---- S = Q K^T (per-thread 4x4) ----
        float s[4][4] = {};
        #pragma unroll 16
        for (int kk = 0; kk < 64; kk++) {
            float4 qv = *(const float4*)&Qt[kk * SSTR + ty * 4];
            float4 kv = *(const float4*)&Kt[kk * SSTR + tx * 4];
            float qa[4] = {qv.x, qv.y, qv.z, qv.w};
            float ka[4] = {kv.x, kv.y, kv.z, kv.w};
            #pragma unroll
            for (int i = 0; i < 4; i++)
                #pragma unroll
                for (int j = 0; j < 4; j++)
                    s[i][j] = fmaf(qa[i], ka[j], s[i][j]);
        }

        // ---- mask + scale (adjacency straight from L2) ----
        #pragma unroll
        for (int i = 0; i < 4; i++) {
            int4 a4 = *(const int4*)&adj[(size_t)(q0 + ty * 4 + i) * SEQ + m0 + tx * 4];
            s[i][0] = a4.x ? s[i][0] * scale : NEG;
            s[i][1] = a4.y ? s[i][1] * scale : NEG;
            s[i][2] = a4.z ? s[i][2] * scale : NEG;
            s[i][3] = a4.w ? s[i][3] * scale : NEG;
        }

        // ---- online softmax (row groups = 16 consecutive lanes) ----
        #pragma unroll
        for (int i = 0; i < 4; i++) {
            float mx = fmaxf(fmaxf(s[i][0], s[i][1]), fmaxf(s[i][2], s[i][3]));
            #pragma unroll
            for (int off = 8; off >= 1; off >>= 1)
                mx = fmaxf(mx, __shfl_xor_sync(0xffffffffu, mx, off));
            float m_new = fmaxf(m_i[i], mx);
            float corr = __expf(m_i[i] - m_new);
            m_i[i] = m_new;
            float rs = 0.f;
            #pragma unroll
            for (int j = 0; j < 4; j++) {
                s[i][j] = __expf(s[i][j] - m_new);
                rs += s[i][j];
            }
            #pragma unroll
            for (int off = 8; off >= 1; off >>= 1)
                rs += __shfl_xor_sync(0xffffffffu, rs, off);
            l_i[i] = l_i[i] * corr + rs;
            #pragma unroll
            for (int j = 0; j < 4; j++) acc[i][j] *= corr;
        }

        // ---- stage P transposed: Pt[c][r] ----
        #pragma unroll
        for (int i = 0; i < 4; i++)
            #pragma unroll
            for (int j = 0; j < 4; j++)
                Pt[(tx * 4 + j) * SSTR + ty * 4 + i] = s[i][j];
        __syncthreads();

        // ---- O += P V ----
        #pragma unroll 16
        for (int c = 0; c < 64; c++) {
            float4 pv = *(const float4*)&Pt[c * SSTR + ty * 4];
            float4 vv = *(const float4*)&Vs[c * SSTR + tx * 4];
            float pa[4] = {pv.x, pv.y, pv.z, pv.w};
            float va[4] = {vv.x, vv.y, vv.z, vv.w};
            #pragma unroll
            for (int i = 0; i < 4; i++)
                #pragma unroll
                for (int j = 0; j < 4; j++)
                    acc[i][j] = fmaf(pa[i], va[j], acc[i][j]);
        }
        __syncthreads();
    }

    // ---- epilogue: normalize, write out [B,N,H*D] ----
    #pragma unroll
    for (int i = 0; i < 4; i++) {
        float inv = 1.0f / l_i[i];
        int n = q0 + ty * 4 + i;
        float4 o;
        o.x = acc[i][0] * inv;
        o.y = acc[i][1] * inv;
        o.z = acc[i][2] * inv;
        o.w = acc[i][3] * inv;
        *(float4*)&out[((size_t)(b * SEQ + n)) * QKV_COLS + hd * OUT_DIM + tx * 4] = o;
    }
}

// ---------------------------------------------------------------------------
// Launch
// ---------------------------------------------------------------------------
extern "C" void kernel_launch(void* const* d_in, const int* in_sizes, int n_in,
                              void* d_out, int out_size)
{
    const int*   adj = (const int*)  d_in[0];
    const float* h   = (const float*)d_in[1];
    const float* Wq  = (const float*)d_in[2];
    const float* bq  = (const float*)d_in[3];
    const float* Wk  = (const float*)d_in[4];
    const float* bk  = (const float*)d_in[5];
    const float* Wv  = (const float*)d_in[6];
    const float* bv  = (const float*)d_in[7];
    float* out = (float*)d_out;

    // projections: grid (cols 512/64, rows 8192/64, {Q,K,V})
    qkv_gemm_kernel<<<dim3(8, 128, 3), 256>>>(h, Wq, bq, Wk, bk, Wv, bv);

    // fused attention
    const int smem_bytes = 4 * 64 * SSTR * (int)sizeof(float);   // ~69.6 KB
    static bool attr_set = false;
    if (!attr_set) {
        cudaFuncSetAttribute(attn_kernel,
                             cudaFuncAttributeMaxDynamicSharedMemorySize, smem_bytes);
        attr_set = true;
    }
    attn_kernel<<<dim3(SEQ / BR, NUM_HEADS, BATCH), 256, smem_bytes>>>(adj, out);
}

// round 3
// speedup vs baseline: 1.1039x; 1.1039x over previous
#include <cuda_runtime.h>
#include <math.h>

#define IN_DIM   256
#define OUT_DIM  64
#define NUM_HEADS 8
#define BATCH    8
#define SEQ      1024
#define QKV_COLS (OUT_DIM * NUM_HEADS)   // 512
#define ROWS     (BATCH * SEQ)           // 8192

// Scratch for projected Q/K/V: [B*N, H*D] each (16 MB apiece).
__device__ float g_Q[ROWS * QKV_COLS];
__device__ float g_K[ROWS * QKV_COLS];
__device__ float g_V[ROWS * QKV_COLS];

// ---------------------------------------------------------------------------
// Kernel 1: QKV projection.  out = h @ W + b
// h: [8192, 256], W: [256, 512].  Block tile 128x128, k-tile 16, thread 8x8.
// blockIdx.z selects Q / K / V.
// ---------------------------------------------------------------------------
__global__ __launch_bounds__(256, 2)
void qkv_gemm_kernel(const float* __restrict__ h,
                     const float* __restrict__ Wq, const float* __restrict__ bq,
                     const float* __restrict__ Wk, const float* __restrict__ bk,
                     const float* __restrict__ Wv, const float* __restrict__ bv)
{
    const int which = blockIdx.z;
    const float* __restrict__ W    = (which == 0) ? Wq : (which == 1) ? Wk : Wv;
    const float* __restrict__ bias = (which == 0) ? bq : (which == 1) ? bk : bv;
    float* __restrict__ out        = (which == 0) ? g_Q : (which == 1) ? g_K : g_V;

    __shared__ float As[16][132];   // k-major A tile  As[k][m], m 0..127
    __shared__ float Bs[16][132];   // Bs[k][n], n 0..127

    const int tid = threadIdx.x;
    const int tx = tid & 15;        // n group (8 cols)
    const int ty = tid >> 4;        // m group (8 rows)
    const int row0 = blockIdx.y * 128;
    const int col0 = blockIdx.x * 128;

    float acc[8][8] = {};

    for (int k0 = 0; k0 < IN_DIM; k0 += 16) {
        // A: 128 rows x 16 k = 512 float4, 2 per thread, stored transposed
        #pragma unroll
        for (int it = 0; it < 2; it++) {
            int lin = it * 256 + tid;          // 0..511
            int r = lin >> 2;                  // 0..127
            int kc = (lin & 3) * 4;            // 0,4,8,12
            float4 a = *(const float4*)&h[(size_t)(row0 + r) * IN_DIM + k0 + kc];
            As[kc + 0][r] = a.x;
            As[kc + 1][r] = a.y;
            As[kc + 2][r] = a.z;
            As[kc + 3][r] = a.w;
        }
        // B: 16 rows x 128 = 512 float4, 2 per thread, natural
        #pragma unroll
        for (int it = 0; it < 2; it++) {
            int lin = it * 256 + tid;
            int r = lin >> 5;                  // 0..15
            int c = (lin & 31) * 4;            // 0..124
            *(float4*)&Bs[r][c] =
                *(const float4*)&W[(size_t)(k0 + r) * QKV_COLS + col0 + c];
        }
        __syncthreads();

        #pragma unroll
        for (int kk = 0; kk < 16; kk++) {
            float4 a0 = *(const float4*)&As[kk][ty * 8];
            float4 a1 = *(const float4*)&As[kk][ty * 8 + 4];
            float4 b0 = *(const float4*)&Bs[kk][tx * 8];
            float4 b1 = *(const float4*)&Bs[kk][tx * 8 + 4];
            float am[8] = {a0.x, a0.y, a0.z, a0.w, a1.x, a1.y, a1.z, a1.w};
            float bn[8] = {b0.x, b0.y, b0.z, b0.w, b1.x, b1.y, b1.z, b1.w};
            #pragma unroll
            for (int i = 0; i < 8; i++)
                #pragma unroll
                for (int j = 0; j < 8; j++)
                    acc[i][j] = fmaf(am[i], bn[j], acc[i][j]);
        }
        __syncthreads();
    }

    // epilogue: + bias, vectorized store (2 float4 per row)
    const int cbase = col0 + tx * 8;
    float4 bv0 = *(const float4*)&bias[cbase];
    float4 bv1 = *(const float4*)&bias[cbase + 4];
    #pragma unroll
    for (int i = 0; i < 8; i++) {
        int r = row0 + ty * 8 + i;
        float4 o0, o1;
        o0.x = acc[i][0] + bv0.x; o0.y = acc[i][1] + bv0.y;
        o0.z = acc[i][2] + bv0.z; o0.w = acc[i][3] + bv0.w;
        o1.x = acc[i][4] + bv1.x; o1.y = acc[i][5] + bv1.y;
        o1.z = acc[i][6] + bv1.z; o1.w = acc[i][7] + bv1.w;
        *(float4*)&out[(size_t)r * QKV_COLS + cbase]     = o0;
        *(float4*)&out[(size_t)r * QKV_COLS + cbase + 4] = o1;
    }
}

// ---------------------------------------------------------------------------
// Kernel 2: fused masked attention (flash-style, fp32).
// One block per (128-query tile, head, batch).  256 threads, 8x4 per thread.
// ---------------------------------------------------------------------------
#define BR 128
#define BC 64
#define RSTR 132                     // stride for [.][r] arrays (r = 0..127)
#define CSTR 68                      // stride for [.][c]/[.][d] arrays (0..63)

__global__ __launch_bounds__(256, 2)
void attn_kernel(const int* __restrict__ adj, float* __restrict__ out)
{
    extern __shared__ float smem[];
    float* Qt = smem;                 // [64][RSTR]  Qt[d][r]
    float* Kt = Qt + 64 * RSTR;       // [64][CSTR]  Kt[d][c]
    float* Vs = Kt + 64 * CSTR;       // [64][CSTR]  Vs[c][d]
    float* Ps = Vs + 64 * CSTR;       // [128][CSTR] Ps[r][c]  (row-major P)

    const int b  = blockIdx.z;
    const int hd = blockIdx.y;
    const int q0 = blockIdx.x * BR;

    const int tid = threadIdx.x;
    const int tx = tid & 15;          // key-col group (4) / dim group (4)
    const int ty = tid >> 4;          // query-row group (8)

    const float* __restrict__ Q = g_Q + ((size_t)b * SEQ) * QKV_COLS + hd * OUT_DIM;
    const float* __restrict__ K = g_K + ((size_t)b * SEQ) * QKV_COLS + hd * OUT_DIM;
    const float* __restrict__ V = g_V + ((size_t)b * SEQ) * QKV_COLS + hd * OUT_DIM;

    // ---- load Q tile transposed: Qt[d][r], 128 rows x 64 d = 2048 float4 ----
    #pragma unroll
    for (int it = 0; it < 8; it++) {
        int lin = it * 256 + tid;            // 0..2047
        int r = lin >> 4;                    // 0..127
        int d = (lin & 15) * 4;
        float4 q = *(const float4*)&Q[(size_t)(q0 + r) * QKV_COLS + d];
        Qt[(d + 0) * RSTR + r] = q.x;
        Qt[(d + 1) * RSTR + r] = q.y;
        Qt[(d + 2) * RSTR + r] = q.z;
        Qt[(d + 3) * RSTR + r] = q.w;
    }

    const float scale = 0.125f;              // 1/sqrt(64)
    const float NEG = -1.0e30f;

    float m_i[8], l_i[8], acc[8][4];
    #pragma unroll
    for (int i = 0; i < 8; i++) {
        m_i[i] = NEG; l_i[i] = 0.f;
        #pragma unroll
        for (int j = 0; j < 4; j++) acc[i][j] = 0.f;
    }

    for (int m0 = 0; m0 < SEQ; m0 += BC) {
        // ---- load K tile transposed + V tile natural (64x64 = 1024 float4) ----
        #pragma unroll
        for (int it = 0; it < 4; it++) {
            int lin = it * 256 + tid;
            int r = lin >> 4;                // 0..63
            int d = (lin & 15) * 4;
            float4 k = *(const float4*)&K[(size_t)(m0 + r) * QKV_COLS + d];
            Kt[(d + 0) * CSTR + r] = k.x;
            Kt[(d + 1) * CSTR + r] = k.y;
            Kt[(d + 2) * CSTR + r] = k.z;
            Kt[(d + 3) * CSTR + r] = k.w;
            float4 v = *(const float4*)&V[(size_t)(m0 + r) * QKV_COLS + d];
            *(float4*)&Vs[r * CSTR + d] = v;
        }
        __syncthreads();

        // ---- S = Q K^T (per-thread 8x4) ----
        float s[8][4] = {};
        #pragma unroll 8
        for (int kk = 0; kk < 64; kk++) {
            float4 q0v = *(const float4*)&Qt[kk * RSTR + ty * 8];
            float4 q1v = *(const float4*)&Qt[kk * RSTR + ty * 8 + 4];
            float4 kv  = *(const float4*)&Kt[kk * CSTR + tx * 4];
            float qa[8] = {q0v.x, q0v.y, q0v.z, q0v.w, q1v.x, q1v.y, q1v.z, q1v.w};
            float ka[4] = {kv.x, kv.y, kv.z, kv.w};
            #pragma unroll
            for (int i = 0; i < 8; i++)
                #pragma unroll
                for (int j = 0; j < 4; j++)
                    s[i][j] = fmaf(qa[i], ka[j], s[i][j]);
        }

        // ---- mask + scale + online softmax + stage P row-major ----
        #pragma unroll
        for (int i = 0; i < 8; i++) {
            int4 a4 = *(const int4*)&adj[(size_t)(q0 + ty * 8 + i) * SEQ + m0 + tx * 4];
            s[i][0] = a4.x ? s[i][0] * scale : NEG;
            s[i][1] = a4.y ? s[i][1] * scale : NEG;
            s[i][2] = a4.z ? s[i][2] * scale : NEG;
            s[i][3] = a4.w ? s[i][3] * scale : NEG;

            float mx = fmaxf(fmaxf(s[i][0], s[i][1]), fmaxf(s[i][2], s[i][3]));
            #pragma unroll
            for (int off = 8; off >= 1; off >>= 1)
                mx = fmaxf(mx, __shfl_xor_sync(0xffffffffu, mx, off));
            float m_new = fmaxf(m_i[i], mx);
            float corr = __expf(m_i[i] - m_new);
            m_i[i] = m_new;
            float rs = 0.f;
            #pragma unroll
            for (int j = 0; j < 4; j++) {
                s[i][j] = __expf(s[i][j] - m_new);
                rs += s[i][j];
            }
            #pragma unroll
            for (int off = 8; off >= 1; off >>= 1)
                rs += __shfl_xor_sync(0xffffffffu, rs, off);
            l_i[i] = l_i[i] * corr + rs;
            #pragma unroll
            for (int j = 0; j < 4; j++) acc[i][j] *= corr;

            *(float4*)&Ps[(ty * 8 + i) * CSTR + tx * 4] =
                make_float4(s[i][0], s[i][1], s[i][2], s[i][3]);
        }
        __syncthreads();

        // ---- O += P V  (P row-major broadcast reads, c chunks of 4) ----
        #pragma unroll 2
        for (int c4 = 0; c4 < BC / 4; c4++) {
            float4 vv[4];
            #pragma unroll
            for (int j = 0; j < 4; j++)
                vv[j] = *(const float4*)&Vs[(c4 * 4 + j) * CSTR + tx * 4];
            #pragma unroll
            for (int i = 0; i < 8; i++) {
                float4 p = *(const float4*)&Ps[(ty * 8 + i) * CSTR + c4 * 4];
                acc[i][0] = fmaf(p.x, vv[0].x, acc[i][0]);
                acc[i][1] = fmaf(p.x, vv[0].y, acc[i][1]);
                acc[i][2] = fmaf(p.x, vv[0].z, acc[i][2]);
                acc[i][3] = fmaf(p.x, vv[0].w, acc[i][3]);
                acc[i][0] = fmaf(p.y, vv[1].x, acc[i][0]);
                acc[i][1] = fmaf(p.y, vv[1].y, acc[i][1]);
                acc[i][2] = fmaf(p.y, vv[1].z, acc[i][2]);
                acc[i][3] = fmaf(p.y, vv[1].w, acc[i][3]);
                acc[i][0] = fmaf(p.z, vv[2].x, acc[i][0]);
                acc[i][1] = fmaf(p.z, vv[2].y, acc[i][1]);
                acc[i][2] = fmaf(p.z, vv[2].z, acc[i][2]);
                acc[i][3] = fmaf(p.z, vv[2].w, acc[i][3]);
                acc[i][0] = fmaf(p.w, vv[3].x, acc[i][0]);
                acc[i][1] = fmaf(p.w, vv[3].y, acc[i][1]);
                acc[i][2] = fmaf(p.w, vv[3].z, acc[i][2]);
                acc[i][3] = fmaf(p.w, vv[3].w, acc[i][3]);
            }
        }
        __syncthreads();
    }

    // ---- epilogue: normalize, write out [B,N,H*D] ----
    #pragma unroll
    for (int i = 0; i < 8; i++) {
        float inv = 1.0f / l_i[i];
        int n = q0 + ty * 8 + i;
        float4 o;
        o.x = acc[i][0] * inv;
        o.y = acc[i][1] * inv;
        o.z = acc[i][2] * inv;
        o.w = acc[i][3] * inv;
        *(float4*)&out[((size_t)(b * SEQ + n)) * QKV_COLS + hd * OUT_DIM + tx * 4] = o;
    }
}

// ---------------------------------------------------------------------------
// Launch
// ---------------------------------------------------------------------------
extern "C" void kernel_launch(void* const* d_in, const int* in_sizes, int n_in,
                              void* d_out, int out_size)
{
    const int*   adj = (const int*)  d_in[0];
    const float* h   = (const float*)d_in[1];
    const float* Wq  = (const float*)d_in[2];
    const float* bq  = (const float*)d_in[3];
    const float* Wk  = (const float*)d_in[4];
    const float* bk  = (const float*)d_in[5];
    const float* Wv  = (const float*)d_in[6];
    const float* bv  = (const float*)d_in[7];
    float* out = (float*)d_out;

    // projections: grid (cols 512/128, rows 8192/128, {Q,K,V})
    qkv_gemm_kernel<<<dim3(4, 64, 3), 256>>>(h, Wq, bq, Wk, bk, Wv, bv);

    // fused attention
    const int smem_bytes = (64 * RSTR + 64 * CSTR + 64 * CSTR + 128 * CSTR)
                           * (int)sizeof(float);   // ~103.4 KB
    static bool attr_set = false;
    if (!attr_set) {
        cudaFuncSetAttribute(attn_kernel,
                             cudaFuncAttributeMaxDynamicSharedMemorySize, smem_bytes);
        attr_set = true;
    }
    attn_kernel<<<dim3(SEQ / BR, NUM_HEADS, BATCH), 256, smem_bytes>>>(adj, out);
}